// round 9
// baseline (speedup 1.0000x reference)
#include <cuda_runtime.h>
#include <cstdint>

// Problem constants
#define B_    64
#define CIN_  64
#define T_    4096
#define F_    128
#define K_    64
#define TOUT_ 4033          // T - K + 1
#define TILE_ 128           // conv outputs per CTA tile
#define SPAN_ 192           // TILE_ + K_ (y values per tile)
#define NT_   32            // ceil(TOUT_/TILE_)
#define NCTA_ (NT_ * B_)    // 2048

#define XS_   192           // x_s row stride (floats)
#define YIL2S 193           // yil row stride (float2): lane word-stride 386 % 32 == 2 -> CF
#define CW2S  65            // cwil row stride (float2): word-stride 130 % 32 == 2 -> CF
#define WSS   64            // ws row stride (floats)
#define CWTOT (64 * 2 * CW2S)   // 8320 ... (half per group: 32 pairs * 130 = 4160)

// smem layout (floats) — total 18000 = 72000 B -> 3 CTAs/SM (72KB granule)
#define OFF_X    0                       // x chunk 16*192 = 3072; cw2 4160 aliases here
#define OFF_WS   4160                    // spatT chunk 16*64 = 1024
#define OFF_YIL  5184                    // 32 * 193 * 2 = 12352
#define OFF_SSQ  17536                   // 192 (+8 pad)
#define OFF_INV  17736                   // 128 (+8 pad)
#define OFF_SACC 17872                   // 128
#define SMEM_FLOATS 18000

__device__ float    g_spatT[CIN_ * F_];     // [c][f] transposed spatial weights
__device__ float    g_cwil[F_ / 2 * 2 * CW2S];  // interleaved conv weights, padded rows
__device__ float    g_wf[F_];
__device__ float    g_acc[B_ * F_];         // per-(b,f) sums (zero-init)
__device__ unsigned g_count;                // CTA completion counter (zero-init)

// ---------------------------------------------------------------------------
// Packed f32x2 FMA (SASS FFMA2 — only reachable via PTX)
// ---------------------------------------------------------------------------
__device__ __forceinline__ float2 ffma2(float2 a, float2 b, float2 c) {
    union U { float2 f; unsigned long long u; };
    U ua{a}, ub{b}, uc{c}, ur;
    asm("fma.rn.f32x2 %0, %1, %2, %3;" : "=l"(ur.u) : "l"(ua.u), "l"(ub.u), "l"(uc.u));
    return ur.f;
}

// ---------------------------------------------------------------------------
// Setup: transpose/interleave weights, per-filter factors
// ---------------------------------------------------------------------------
__global__ void setup_kernel(const float* __restrict__ conv_w,
                             const float* __restrict__ spat_w,
                             const float* __restrict__ weight) {
    int f = threadIdx.x;  // 128 threads
    float sc = 0.f, ss = 0.f;
    #pragma unroll 8
    for (int k = 0; k < K_; k++) {
        float v = conv_w[f * K_ + k];
        sc += v * v;
        g_cwil[(f >> 1) * (2 * CW2S) + 2 * k + (f & 1)] = v;
    }
    #pragma unroll 8
    for (int c = 0; c < CIN_; c++) {
        float v = spat_w[f * CIN_ + c];
        ss += v * v;
        g_spatT[c * F_ + f] = v;
    }
    // scale = sqrt(CIN*K) = 64 exactly; fold 1/Tout for the mean
    g_wf[f] = weight[f] * 64.0f / (sqrtf(sc) * sqrtf(ss) * (float)TOUT_);
}

// ---------------------------------------------------------------------------
// Main fused kernel: one CTA per (t-tile, batch); last CTA finishes.
// ---------------------------------------------------------------------------
__global__ __launch_bounds__(256, 3)
void main_kernel(const float* __restrict__ x,
                 const float* __restrict__ bias,
                 float* __restrict__ out) {
    extern __shared__ float sm[];
    float*  x_s  = sm + OFF_X;                // [16 c][XS_]
    float2* cw2  = (float2*)(sm + OFF_X);     // aliases x (temporal phase)
    float*  ws   = sm + OFF_WS;               // [16 c][64 f]
    float2* yil2 = (float2*)(sm + OFF_YIL);   // [32 pairs][YIL2S f2]
    float*  ssq  = sm + OFF_SSQ;              // [192]
    float*  invn = sm + OFF_INV;              // [128]
    float*  sacc = sm + OFF_SACC;             // [128]
    __shared__ unsigned sflag;

    const int tid  = threadIdx.x;
    const int b    = blockIdx.y;
    const int tile = blockIdx.x;
    const int t0g  = tile * TILE_;
    const int warp = tid >> 5;
    const int lane = tid & 31;

    const float* xb = x + (size_t)b * CIN_ * T_;
    const float4 z4 = make_float4(0.f, 0.f, 0.f, 0.f);

    if (tid < F_) sacc[tid] = 0.f;
    if (tid < SPAN_) ssq[tid] = 0.f;

    // spatial 2-D warp grid: 4 filter-groups x 2 t-halves
    const int wf4   = warp & 3;          // 16 filters
    const int wt    = warp >> 2;         // 96-t half
    const int tbase = 96 * wt;
    const int tt    = lane & 7;          // 8 t-columns (quads)
    const int fr    = lane >> 3;         // 4 filter-rows
    const int fthl  = 16 * wf4 + 4 * fr; // thread's first filter within group
    const int tq0   = tbase + 4 * tt;

    // temporal mapping: pair = lane; warp -> 16 t
    const int t0c = 16 * warp;

    for (int g = 0; g < 2; g++) {
        const int gbase = 64 * g;

        float2 acc[4][6];
        #pragma unroll
        for (int fi = 0; fi < 4; fi++)
            #pragma unroll
            for (int j = 0; j < 6; j++) acc[fi][j] = make_float2(0.f, 0.f);

        #pragma unroll
        for (int cb = 0; cb < 4; cb++) {        // 16-channel chunks
            const int c0 = 16 * cb;
            __syncthreads();   // region free of previous readers

            // stage x chunk: 16 c x 192 t (768 float4, 3 per thread)
            #pragma unroll
            for (int r = 0; r < 3; r++) {
                int q  = r * 256 + tid;          // 0..767
                int cc = q / 48;
                int tl = (q % 48) * 4;
                int tg = t0g + tl;
                float4 v = (tg + 3 < T_)
                    ? *(const float4*)(xb + (size_t)(c0 + cc) * T_ + tg) : z4;
                *(float4*)(x_s + cc * XS_ + tl) = v;
            }
            // stage spatT chunk: ws[c][f] = g_spatT[(c0+c)*128 + gbase+f]
            #pragma unroll
            for (int r = 0; r < 4; r++) {
                int idx = r * 256 + tid;         // 0..1023
                int cc = idx >> 6, f = idx & 63;
                ws[cc * WSS + f] = g_spatT[(c0 + cc) * F_ + gbase + f];
            }
            __syncthreads();

            // ssq partials (group 0 only; x identical across groups)
            if (g == 0 && tid < SPAN_) {
                float s = 0.f;
                #pragma unroll 4
                for (int cc = 0; cc < 16; cc++) {
                    float v = x_s[cc * XS_ + tid];
                    s += v * v;
                }
                ssq[tid] += s;
            }

            // spatial GEMM partial: 4 filters x 12 t per thread
            #pragma unroll 2
            for (int cc = 0; cc < 16; cc++) {
                const float* xr = x_s + cc * XS_ + tq0;
                float4 x0 = *(const float4*)(xr);
                float4 x1 = *(const float4*)(xr + 32);
                float4 x2 = *(const float4*)(xr + 64);
                float4 w4 = *(const float4*)(ws + cc * WSS + fthl);
                float2 xp[6] = { make_float2(x0.x, x0.y), make_float2(x0.z, x0.w),
                                 make_float2(x1.x, x1.y), make_float2(x1.z, x1.w),
                                 make_float2(x2.x, x2.y), make_float2(x2.z, x2.w) };
                float wv[4] = { w4.x, w4.y, w4.z, w4.w };
                #pragma unroll
                for (int fi = 0; fi < 4; fi++) {
                    float2 s = make_float2(wv[fi], wv[fi]);
                    #pragma unroll
                    for (int j = 0; j < 6; j++)
                        acc[fi][j] = ffma2(s, xp[j], acc[fi][j]);
                }
            }
        }

        // ---- store filter-interleaved y: yil2[p][t] = (y_even[t], y_odd[t]) ----
        {
            const int p0 = fthl >> 1;
            #pragma unroll
            for (int pi = 0; pi < 2; pi++) {
                float2* yr = yil2 + (p0 + pi) * YIL2S;
                const int fa = 2 * pi, fb = 2 * pi + 1;
                #pragma unroll
                for (int q = 0; q < 3; q++) {
                    const int tq = tq0 + 32 * q;
                    float2 ea = acc[fa][2 * q],     eb = acc[fb][2 * q];
                    float2 ca = acc[fa][2 * q + 1], cb2 = acc[fb][2 * q + 1];
                    yr[tq]     = make_float2(ea.x, eb.x);
                    yr[tq + 1] = make_float2(ea.y, eb.y);
                    yr[tq + 2] = make_float2(ca.x, cb2.x);
                    yr[tq + 3] = make_float2(ca.y, cb2.y);
                }
            }
        }
        __syncthreads();   // yil complete; x_s/ws reads done

        // ---- stage interleaved conv weights into cw2 (aliases x_s) + invn ----
        {
            const int base = g * (32 * 2 * CW2S) / 2;   // float2 offset per group
            #pragma unroll
            for (int r = 0; r < 9; r++) {
                int idx = r * 256 + tid;                // 0..2303, need 2080 f2
                if (idx < 32 * CW2S)
                    cw2[idx] = ((const float2*)g_cwil)[base + idx];
            }
        }
        if (g == 0 && tid < TILE_) {
            float s = 0.f;
            #pragma unroll 8
            for (int k = 0; k < K_; k++) s += ssq[tid + k];
            invn[tid] = ((t0g + tid) < TOUT_ && s > 0.f) ? rsqrtf(s) : 0.f;
        }
        __syncthreads();

        // ---- temporal conv: 16 t per warp, modular 16-slot window ----
        {
            const float2* yr  = yil2 + lane * YIL2S;
            const float2* cwr = cw2 + lane * CW2S;

            float2 tacc[16];
            #pragma unroll
            for (int i = 0; i < 16; i++) tacc[i] = make_float2(0.f, 0.f);

            float2 w2[16];
            #pragma unroll
            for (int i = 0; i < 16; i++) w2[i] = yr[t0c + i];

            for (int ko = 0; ko < 4; ko++) {
                #pragma unroll
                for (int ku = 0; ku < 16; ku++) {
                    const int k = 16 * ko + ku;
                    float2 s = cwr[k];
                    #pragma unroll
                    for (int i = 0; i < 16; i++)
                        tacc[i] = ffma2(s, w2[(ku + i) & 15], tacc[i]);
                    // refill: slot (k&15) <- y[t0c+k+16]  (max idx 191 < 193)
                    w2[ku] = yr[t0c + k + 16];
                }
            }

            float pe = 0.f, po = 0.f;
            #pragma unroll
            for (int i = 0; i < 16; i++) {
                float iv = invn[t0c + i];   // 0 kills t >= TOUT and padded region
                pe += fabsf(tacc[i].x) * iv;
                po += fabsf(tacc[i].y) * iv;
            }
            atomicAdd(&sacc[gbase + 2 * lane],     pe);
            atomicAdd(&sacc[gbase + 2 * lane + 1], po);
        }
    }

    // ---- one gmem atomic per filter ----
    __syncthreads();
    if (tid < F_) atomicAdd(&g_acc[b * F_ + tid], sacc[tid]);

    // ---- last-CTA finish: apply per-filter weight factors + bias; reset ----
    __threadfence();
    __syncthreads();
    if (tid == 0) {
        unsigned old = atomicAdd(&g_count, 1u);
        sflag = (old == NCTA_ - 1) ? 1u : 0u;
    }
    __syncthreads();
    if (sflag) {
        if (tid < B_) {
            float s = 0.f;
            #pragma unroll 8
            for (int f = 0; f < F_; f++)
                s += bias[f] + g_wf[f] * __ldcg(&g_acc[tid * F_ + f]);
            out[tid] = s;
        }
        __syncthreads();
        for (int i = tid; i < B_ * F_; i += 256) g_acc[i] = 0.f;
        if (tid == 0) g_count = 0u;
    }
}

// ---------------------------------------------------------------------------
extern "C" void kernel_launch(void* const* d_in, const int* in_sizes, int n_in,
                              void* d_out, int out_size) {
    const float* x      = (const float*)d_in[0];  // [64,64,4096]
    const float* conv_w = (const float*)d_in[1];  // [128,64]
    const float* spat_w = (const float*)d_in[2];  // [128,64]
    const float* weight = (const float*)d_in[3];  // [128]
    const float* bias   = (const float*)d_in[4];  // [128]
    float* out = (float*)d_out;                   // [64]

    cudaFuncSetAttribute(main_kernel,
                         cudaFuncAttributeMaxDynamicSharedMemorySize,
                         SMEM_FLOATS * sizeof(float));

    setup_kernel<<<1, 128>>>(conv_w, spat_w, weight);
    dim3 grid(NT_, B_);
    main_kernel<<<grid, 256, SMEM_FLOATS * sizeof(float)>>>(x, bias, out);
}

// round 10
// speedup vs baseline: 1.2229x; 1.2229x over previous
#include <cuda_runtime.h>
#include <cstdint>

// Problem constants
#define B_    64
#define CIN_  64
#define T_    4096
#define F_    128
#define K_    64
#define TOUT_ 4033
#define NPAIR 64

// ---- kernel 1 (spatial) ----
#define T1_   64
#define NT1_  64                  // 4096 / 64
#define XS1_  68                  // x row stride (floats)
#define WD2S_ 130                 // wdup row stride (float2)
#define O1_X   0                  // 16*68 = 1088 floats
#define O1_W   1088               // 16*130 f2 = 4160 floats
#define O1_SSQ 5248               // 64 floats (+pad)
#define SM1_FLOATS 5320           // 21280 B -> 4 CTAs/SM

// ---- kernel 2 (temporal) ----
#define T2_   128
#define NT2_  32
#define NCTA2_ (NT2_ * 2 * B_)    // 4096
#define YIL2S 193                 // y tile row stride (float2)
#define CW2S  65                  // cw row stride (float2)
#define O2_Y    0                 // 32*193 f2 = 12352 floats
#define O2_CW   12352             // 32*65 f2 = 4160 floats
#define O2_SSQ  16512             // 192 (+pad)
#define O2_INV  16712             // 128
#define O2_SACC 16840             // 64
#define SM2_FLOATS 16912          // 67648 B -> 3 CTAs/SM

__device__ __align__(16) float2 g_y[(size_t)B_ * NPAIR * T_];  // [b][pair][t]
__device__ float    g_ssq[B_ * T_];
__device__ __align__(16) float2 g_wdup[CIN_ * F_];   // [c][f] = (w,w)
__device__ __align__(16) float  g_cwil[NPAIR * 2 * CW2S];  // [pair][2k+parity]
__device__ float    g_wf[F_];
__device__ float    g_acc[B_ * F_];      // zero-init; reset by last CTA
__device__ unsigned g_count;             // zero-init; reset by last CTA

// ---------------------------------------------------------------------------
// Packed f32x2 FMA (SASS FFMA2 — only reachable via PTX)
// ---------------------------------------------------------------------------
__device__ __forceinline__ float2 ffma2(float2 a, float2 b, float2 c) {
    union U { float2 f; unsigned long long u; };
    U ua{a}, ub{b}, uc{c}, ur;
    asm("fma.rn.f32x2 %0, %1, %2, %3;" : "=l"(ur.u) : "l"(ua.u), "l"(ub.u), "l"(uc.u));
    return ur.f;
}

// ---------------------------------------------------------------------------
// Setup: duplicate/interleave weights, per-filter combined factor
// ---------------------------------------------------------------------------
__global__ void setup_kernel(const float* __restrict__ conv_w,
                             const float* __restrict__ spat_w,
                             const float* __restrict__ weight) {
    int f = threadIdx.x;  // 128 threads
    float sc = 0.f, ss = 0.f;
    #pragma unroll 8
    for (int k = 0; k < K_; k++) {
        float v = conv_w[f * K_ + k];
        sc += v * v;
        g_cwil[(f >> 1) * (2 * CW2S) + 2 * k + (f & 1)] = v;
    }
    #pragma unroll 8
    for (int c = 0; c < CIN_; c++) {
        float v = spat_w[f * CIN_ + c];
        ss += v * v;
        g_wdup[c * F_ + f] = make_float2(v, v);
    }
    // scale = sqrt(CIN*K) = 64 exactly; fold 1/Tout for the mean
    g_wf[f] = weight[f] * 64.0f / (sqrtf(sc) * sqrtf(ss) * (float)TOUT_);
}

// ---------------------------------------------------------------------------
// Kernel 1: spatial GEMM y[b][f][t] = sum_c w[f,c] x[b,c,t]  + ssq
// grid (NT1_, B_), 256 threads. No OOB anywhere (64*64 = 4096 exact).
// ---------------------------------------------------------------------------
__global__ __launch_bounds__(256, 4)
void k1_spatial(const float* __restrict__ x) {
    extern __shared__ float sm[];
    float* x_s   = sm + O1_X;     // [16 c][XS1_]
    float* ws    = sm + O1_W;     // [16 c][WD2S_ f2] duplicated weights
    float* ssq_s = sm + O1_SSQ;   // [64]

    const int tid  = threadIdx.x;
    const int b    = blockIdx.y;
    const int t0g  = blockIdx.x * T1_;
    const int warp = tid >> 5;
    const int lane = tid & 31;

    const int wf4  = warp & 3;           // filter group (16 filters)
    const int wt   = warp >> 2;          // t half (32 t)
    const int tt   = lane & 7;
    const int fr   = lane >> 3;
    const int fthl = 16 * wf4 + 4 * fr;  // first filter within 64-group
    const int tq0  = 32 * wt + 4 * tt;   // local t quad

    const float* xb = x + (size_t)b * CIN_ * T_ + t0g;

    if (tid < T1_) ssq_s[tid] = 0.f;

    float2 acc[2][4][2];
    #pragma unroll
    for (int g = 0; g < 2; g++)
        #pragma unroll
        for (int fi = 0; fi < 4; fi++)
            #pragma unroll
            for (int j = 0; j < 2; j++) acc[g][fi][j] = make_float2(0.f, 0.f);

    for (int cb = 0; cb < 4; cb++) {
        const int c0 = 16 * cb;
        __syncthreads();
        // stage x: 16 c x 64 t = 256 float4 (1 per thread)
        {
            int cc = tid >> 4, t4 = (tid & 15) * 4;
            *(float4*)(x_s + cc * XS1_ + t4) =
                *(const float4*)(xb + (size_t)(c0 + cc) * T_ + t4);
        }
        // stage wdup: 16 c x 128 f2 = 1024 float4 (4 per thread)
        #pragma unroll
        for (int r = 0; r < 4; r++) {
            int idx = r * 256 + tid;
            int cc = idx >> 6, q = idx & 63;
            *(float4*)(ws + cc * (2 * WD2S_) + q * 4) =
                *(const float4*)((const float*)(g_wdup + (size_t)(c0 + cc) * F_) + q * 4);
        }
        __syncthreads();

        if (tid < T1_) {
            float s = 0.f;
            #pragma unroll 4
            for (int cc = 0; cc < 16; cc++) {
                float v = x_s[cc * XS1_ + tid];
                s += v * v;
            }
            ssq_s[tid] += s;
        }

        #pragma unroll
        for (int cc = 0; cc < 16; cc++) {
            float4 xq = *(const float4*)(x_s + cc * XS1_ + tq0);
            float2 xp0 = make_float2(xq.x, xq.y);
            float2 xp1 = make_float2(xq.z, xq.w);
            const float* wr = ws + cc * (2 * WD2S_);
            #pragma unroll
            for (int g = 0; g < 2; g++) {
                float4 wa = *(const float4*)(wr + 2 * (64 * g + fthl));
                float4 wb = *(const float4*)(wr + 2 * (64 * g + fthl) + 4);
                float2 w0 = make_float2(wa.x, wa.y);
                float2 w1 = make_float2(wa.z, wa.w);
                float2 w2 = make_float2(wb.x, wb.y);
                float2 w3 = make_float2(wb.z, wb.w);
                acc[g][0][0] = ffma2(w0, xp0, acc[g][0][0]);
                acc[g][0][1] = ffma2(w0, xp1, acc[g][0][1]);
                acc[g][1][0] = ffma2(w1, xp0, acc[g][1][0]);
                acc[g][1][1] = ffma2(w1, xp1, acc[g][1][1]);
                acc[g][2][0] = ffma2(w2, xp0, acc[g][2][0]);
                acc[g][2][1] = ffma2(w2, xp1, acc[g][2][1]);
                acc[g][3][0] = ffma2(w3, xp0, acc[g][3][0]);
                acc[g][3][1] = ffma2(w3, xp1, acc[g][3][1]);
            }
        }
    }

    // write filter-interleaved y: g_y[b][P][t] = (y_{2P}[t], y_{2P+1}[t])
    {
        const size_t ybase = (size_t)b * NPAIR * T_;
        #pragma unroll
        for (int g = 0; g < 2; g++) {
            const int P0 = 32 * g + (fthl >> 1);
            #pragma unroll
            for (int pi = 0; pi < 2; pi++) {
                float2 a0 = acc[g][2 * pi][0], a1 = acc[g][2 * pi + 1][0];
                float2 b0 = acc[g][2 * pi][1], b1 = acc[g][2 * pi + 1][1];
                float2* dst = g_y + ybase + (size_t)(P0 + pi) * T_ + t0g + tq0;
                *(float4*)dst       = make_float4(a0.x, a1.x, a0.y, a1.y);
                *(float4*)(dst + 2) = make_float4(b0.x, b1.x, b0.y, b1.y);
            }
        }
    }
    if (tid < T1_) g_ssq[b * T_ + t0g + tid] = ssq_s[tid];
}

// ---------------------------------------------------------------------------
// Kernel 2: temporal conv + |.|*invn reduction; last CTA finishes.
// grid (NT2_, 2, B_), 256 threads.
// ---------------------------------------------------------------------------
__global__ __launch_bounds__(256, 3)
void k2_temporal(const float* __restrict__ bias,
                 float* __restrict__ out) {
    extern __shared__ float sm[];
    float2* yil2 = (float2*)(sm + O2_Y);    // [32 pairs][YIL2S]
    float2* cw2  = (float2*)(sm + O2_CW);   // [32 pairs][CW2S]
    float*  ssqs = sm + O2_SSQ;             // [192]
    float*  invn = sm + O2_INV;             // [128]
    float*  sacc = sm + O2_SACC;            // [64]
    __shared__ unsigned sflag;

    const int tid  = threadIdx.x;
    const int tile = blockIdx.x;
    const int h    = blockIdx.y;            // filter half (64 filters)
    const int b    = blockIdx.z;
    const int t0g  = tile * T2_;
    const int warp = tid >> 5;
    const int lane = tid & 31;
    const int t0c  = 16 * warp;

    if (tid < 64) sacc[tid] = 0.f;

    // stage cw (2080 f2, contiguous)
    #pragma unroll
    for (int r = 0; r < 9; r++) {
        int idx = r * 256 + tid;
        if (idx < 32 * CW2S)
            cw2[idx] = ((const float2*)g_cwil)[h * 32 * CW2S + idx];
    }
    // stage ssq (192, guarded)
    if (tid < 192) {
        int tg = t0g + tid;
        ssqs[tid] = (tg < T_) ? g_ssq[b * T_ + tg] : 0.f;
    }
    // stage y tile: 32 pairs x 192 t (guarded zero-fill)
    {
        const float2* ysrc = g_y + (size_t)(b * NPAIR + 32 * h) * T_;
        #pragma unroll
        for (int r = 0; r < 24; r++) {
            int idx = r * 256 + tid;          // 0..6143
            int p = idx / 192, t = idx - p * 192;
            int tg = t0g + t;
            yil2[p * YIL2S + t] = (tg < T_)
                ? ysrc[(size_t)p * T_ + tg] : make_float2(0.f, 0.f);
        }
    }
    __syncthreads();

    if (tid < T2_) {
        float s = 0.f;
        #pragma unroll 8
        for (int k = 0; k < K_; k++) s += ssqs[tid + k];
        invn[tid] = ((t0g + tid) < TOUT_ && s > 0.f) ? rsqrtf(s) : 0.f;
    }
    __syncthreads();

    // temporal conv: lane = pair, warp -> 16 t, modular 16-slot window
    {
        const float2* yr  = yil2 + lane * YIL2S;
        const float2* cwr = cw2 + lane * CW2S;

        float2 tacc[16];
        #pragma unroll
        for (int i = 0; i < 16; i++) tacc[i] = make_float2(0.f, 0.f);

        float2 w2[16];
        #pragma unroll
        for (int i = 0; i < 16; i++) w2[i] = yr[t0c + i];

        for (int ko = 0; ko < 4; ko++) {
            #pragma unroll
            for (int ku = 0; ku < 16; ku++) {
                const int k = 16 * ko + ku;
                float2 s = cwr[k];
                #pragma unroll
                for (int i = 0; i < 16; i++)
                    tacc[i] = ffma2(s, w2[(ku + i) & 15], tacc[i]);
                // refill: slot (k&15) <- y[t0c+k+16]  (max idx 191 < 193)
                w2[ku] = yr[t0c + k + 16];
            }
        }

        float pe = 0.f, po = 0.f;
        #pragma unroll
        for (int i = 0; i < 16; i++) {
            float iv = invn[t0c + i];   // 0 kills t >= TOUT and padded region
            pe += fabsf(tacc[i].x) * iv;
            po += fabsf(tacc[i].y) * iv;
        }
        atomicAdd(&sacc[2 * lane],     pe);
        atomicAdd(&sacc[2 * lane + 1], po);
    }

    __syncthreads();
    if (tid < 64) atomicAdd(&g_acc[b * F_ + 64 * h + tid], sacc[tid]);

    // ---- last-CTA finish ----
    __threadfence();
    __syncthreads();
    if (tid == 0) {
        unsigned old = atomicAdd(&g_count, 1u);
        sflag = (old == NCTA2_ - 1) ? 1u : 0u;
    }
    __syncthreads();
    if (sflag) {
        if (tid < B_) {
            float s = 0.f;
            #pragma unroll 8
            for (int f = 0; f < F_; f++)
                s += bias[f] + g_wf[f] * __ldcg(&g_acc[tid * F_ + f]);
            out[tid] = s;
        }
        __syncthreads();
        for (int i = tid; i < B_ * F_; i += 256) g_acc[i] = 0.f;
        if (tid == 0) g_count = 0u;
    }
}

// ---------------------------------------------------------------------------
extern "C" void kernel_launch(void* const* d_in, const int* in_sizes, int n_in,
                              void* d_out, int out_size) {
    const float* x      = (const float*)d_in[0];  // [64,64,4096]
    const float* conv_w = (const float*)d_in[1];  // [128,64]
    const float* spat_w = (const float*)d_in[2];  // [128,64]
    const float* weight = (const float*)d_in[3];  // [128]
    const float* bias   = (const float*)d_in[4];  // [128]
    float* out = (float*)d_out;                   // [64]

    cudaFuncSetAttribute(k1_spatial,
                         cudaFuncAttributeMaxDynamicSharedMemorySize,
                         SM1_FLOATS * sizeof(float));
    cudaFuncSetAttribute(k2_temporal,
                         cudaFuncAttributeMaxDynamicSharedMemorySize,
                         SM2_FLOATS * sizeof(float));

    setup_kernel<<<1, 128>>>(conv_w, spat_w, weight);

    dim3 g1(NT1_, B_);
    k1_spatial<<<g1, 256, SM1_FLOATS * sizeof(float)>>>(x);

    dim3 g2(NT2_, 2, B_);
    k2_temporal<<<g2, 256, SM2_FLOATS * sizeof(float)>>>(bias, out);
}

// round 13
// speedup vs baseline: 1.5320x; 1.2528x over previous
#include <cuda_runtime.h>
#include <cstdint>

// Problem constants
#define B_    64
#define CIN_  64
#define T_    4096
#define F_    128
#define K_    64
#define TOUT_ 4033
#define NPAIR 64

// ---- K1 (spatial GEMM) ----
#define T1_   64
#define NT1_  64                  // 4096 / 64
#define WSS   132                 // weight row stride (floats): holds 128 f, mult of 4
#define XSS   68                  // x row stride (floats)
#define O1_W   0                  // ws 64*132 = 8448
#define O1_X   8448               // x  64*68  = 4352
#define O1_SSQ 12800              // 64 (+pad)
#define SM1_FLOATS 12872          // 51488 B -> 3 CTAs/SM

// ---- K2 (temporal) ----
#define T2_   128
#define NT2_  32
#define NCTA2_ (NT2_ * 2 * B_)    // 4096
#define YIL2S 193                 // y tile row stride (float2)
#define CW2S  65                  // cw row stride (float2)
#define O2_Y    0                 // 32*193 f2 = 12352 floats
#define O2_CW   12352             // 32*65 f2 = 4160 floats
#define O2_SSQ  16512             // 192 (+pad)
#define O2_INV  16712             // 128
#define O2_SACC 16840             // 64
#define SM2_FLOATS 16912          // 67648 B -> 3 CTAs/SM

__device__ __align__(16) float2 g_y[(size_t)B_ * NPAIR * T_];  // [b][pair][t]
__device__ float    g_ssq[B_ * T_];
__device__ float    g_acc[B_ * F_];      // zero-init; reset by last CTA
__device__ unsigned g_count;             // zero-init; reset by last CTA

// ---------------------------------------------------------------------------
// Packed f32x2 FMA (SASS FFMA2 — only reachable via PTX)
// ---------------------------------------------------------------------------
__device__ __forceinline__ float2 ffma2(float2 a, float2 b, float2 c) {
    union U { float2 f; unsigned long long u; };
    U ua{a}, ub{b}, uc{c}, ur;
    asm("fma.rn.f32x2 %0, %1, %2, %3;" : "=l"(ur.u) : "l"(ua.u), "l"(ub.u), "l"(uc.u));
    return ur.f;
}

// ---------------------------------------------------------------------------
// K1: spatial GEMM y[b][f][t] = sum_c w[f,c] x[b,c,t]  + ssq
// grid (NT1_, B_), 256 threads. No OOB anywhere (64*64 = 4096 exact).
// ---------------------------------------------------------------------------
__global__ __launch_bounds__(256, 3)
void k1_spatial(const float* __restrict__ x,
                const float* __restrict__ spat_w) {
    extern __shared__ float sm[];
    float* ws  = sm + O1_W;       // [64 c][WSS] transposed spat weights (128 f)
    float* x_s = sm + O1_X;       // [64 c][XSS]

    const int tid  = threadIdx.x;
    const int b    = blockIdx.y;
    const int t0g  = blockIdx.x * T1_;
    const int warp = tid >> 5;
    const int lane = tid & 31;

    const int wf4  = warp & 3;           // filter group (16 filters)
    const int wt   = warp >> 2;          // t half (32 t)
    const int tt   = lane & 7;
    const int fr   = lane >> 3;
    const int fthl = 16 * wf4 + 4 * fr;  // first filter within 64-group (even)
    const int tq0  = 32 * wt + 4 * tt;   // local t quad

    // ---- stage transposed weights: ws[c*WSS + f] = spat_w[f*64 + c] ----
    #pragma unroll
    for (int r = 0; r < 32; r++) {
        int idx = r * 256 + tid;         // 0..8191, coalesced read
        int f = idx >> 6, c = idx & 63;
        ws[c * WSS + f] = spat_w[idx];
    }
    // ---- stage x tile: 64 c x 64 t (1024 float4, 4 per thread) ----
    #pragma unroll
    for (int r = 0; r < 4; r++) {
        int q = r * 256 + tid;           // 0..1023
        int c = q >> 4, t4 = (q & 15) * 4;
        *(float4*)(x_s + c * XSS + t4) =
            *(const float4*)(x + (size_t)(b * CIN_ + c) * T_ + t0g + t4);
    }
    __syncthreads();

    if (tid < T1_) {
        float s = 0.f;
        #pragma unroll 8
        for (int c = 0; c < CIN_; c++) {
            float v = x_s[c * XSS + tid];
            s += v * v;
        }
        g_ssq[b * T_ + t0g + tid] = s;
    }

    float2 acc[2][4][2];
    #pragma unroll
    for (int g = 0; g < 2; g++)
        #pragma unroll
        for (int fi = 0; fi < 4; fi++)
            #pragma unroll
            for (int j = 0; j < 2; j++) acc[g][fi][j] = make_float2(0.f, 0.f);

    #pragma unroll 2
    for (int c = 0; c < CIN_; c++) {
        float4 xq = *(const float4*)(x_s + c * XSS + tq0);
        float2 xp0 = make_float2(xq.x, xq.y);
        float2 xp1 = make_float2(xq.z, xq.w);
        const float* wr = ws + c * WSS;
        #pragma unroll
        for (int g = 0; g < 2; g++) {
            float4 w4 = *(const float4*)(wr + 64 * g + fthl);
            float2 s0 = make_float2(w4.x, w4.x);
            float2 s1 = make_float2(w4.y, w4.y);
            float2 s2 = make_float2(w4.z, w4.z);
            float2 s3 = make_float2(w4.w, w4.w);
            acc[g][0][0] = ffma2(s0, xp0, acc[g][0][0]);
            acc[g][0][1] = ffma2(s0, xp1, acc[g][0][1]);
            acc[g][1][0] = ffma2(s1, xp0, acc[g][1][0]);
            acc[g][1][1] = ffma2(s1, xp1, acc[g][1][1]);
            acc[g][2][0] = ffma2(s2, xp0, acc[g][2][0]);
            acc[g][2][1] = ffma2(s2, xp1, acc[g][2][1]);
            acc[g][3][0] = ffma2(s3, xp0, acc[g][3][0]);
            acc[g][3][1] = ffma2(s3, xp1, acc[g][3][1]);
        }
    }

    // write filter-interleaved y: g_y[b][P][t] = (y_{2P}[t], y_{2P+1}[t])
    {
        const size_t ybase = (size_t)b * NPAIR * T_;
        #pragma unroll
        for (int g = 0; g < 2; g++) {
            const int P0 = 32 * g + (fthl >> 1);
            #pragma unroll
            for (int pi = 0; pi < 2; pi++) {
                float2 a0 = acc[g][2 * pi][0], a1 = acc[g][2 * pi + 1][0];
                float2 b0 = acc[g][2 * pi][1], b1 = acc[g][2 * pi + 1][1];
                float2* dst = g_y + ybase + (size_t)(P0 + pi) * T_ + t0g + tq0;
                *(float4*)dst       = make_float4(a0.x, a1.x, a0.y, a1.y);
                *(float4*)(dst + 2) = make_float4(b0.x, b1.x, b0.y, b1.y);
            }
        }
    }
}

// ---------------------------------------------------------------------------
// K2: temporal conv + |.|*invn reduction; last CTA finishes.
// grid (NT2_, 2, B_), 256 threads.
// ---------------------------------------------------------------------------
__global__ __launch_bounds__(256, 3)
void k2_temporal(const float* __restrict__ conv_w,
                 const float* __restrict__ spat_w,
                 const float* __restrict__ weight,
                 const float* __restrict__ bias,
                 float* __restrict__ out) {
    extern __shared__ float sm2[];
    float2* yil2 = (float2*)(sm2 + O2_Y);    // [32 pairs][YIL2S]
    float2* cw2  = (float2*)(sm2 + O2_CW);   // [32 pairs][CW2S]
    float*  ssqs = sm2 + O2_SSQ;             // [192]
    float*  invn = sm2 + O2_INV;             // [128]
    float*  sacc = sm2 + O2_SACC;            // [64]
    __shared__ unsigned sflag;

    const int tid  = threadIdx.x;
    const int tile = blockIdx.x;
    const int h    = blockIdx.y;             // filter half (64 filters)
    const int b    = blockIdx.z;
    const int t0g  = tile * T2_;
    const int warp = tid >> 5;
    const int lane = tid & 31;
    const int t0c  = 16 * warp;

    if (tid < 64) sacc[tid] = 0.f;

    // ---- stage interleaved conv weights from raw conv_w (coalesced LDG) ----
    #pragma unroll
    for (int r = 0; r < 16; r++) {
        int idx = r * 256 + tid;             // 0..4095
        int fl = idx >> 6, k = idx & 63;
        float v = conv_w[(64 * h + fl) * K_ + k];
        ((float*)cw2)[(fl >> 1) * (2 * CW2S) + 2 * k + (fl & 1)] = v;
    }
    // ---- stage ssq (guarded) ----
    if (tid < 192) {
        int tg = t0g + tid;
        ssqs[tid] = (tg < T_) ? g_ssq[b * T_ + tg] : 0.f;
    }
    // ---- stage y tile (warp-strided, guarded zero-fill) ----
    {
        const float2* ysrc = g_y + (size_t)(b * NPAIR + 32 * h) * T_ + t0g;
        #pragma unroll
        for (int p = warp; p < 32; p += 8) {
            const float2* yp = ysrc + (size_t)p * T_;
            #pragma unroll
            for (int t = lane; t < 192; t += 32)
                yil2[p * YIL2S + t] = (t0g + t < T_)
                    ? yp[t] : make_float2(0.f, 0.f);
        }
    }
    __syncthreads();

    if (tid < T2_) {
        float s = 0.f;
        #pragma unroll 8
        for (int k = 0; k < K_; k++) s += ssqs[tid + k];
        invn[tid] = ((t0g + tid) < TOUT_ && s > 0.f) ? rsqrtf(s) : 0.f;
    }
    __syncthreads();

    // ---- temporal conv: lane = pair, warp -> 16 t, modular 16-slot window ----
    {
        const float2* yr  = yil2 + lane * YIL2S;
        const float2* cwr = cw2 + lane * CW2S;

        float2 tacc[16];
        #pragma unroll
        for (int i = 0; i < 16; i++) tacc[i] = make_float2(0.f, 0.f);

        float2 w2[16];
        #pragma unroll
        for (int i = 0; i < 16; i++) w2[i] = yr[t0c + i];

        for (int ko = 0; ko < 4; ko++) {
            #pragma unroll
            for (int ku = 0; ku < 16; ku++) {
                const int k = 16 * ko + ku;
                float2 s = cwr[k];
                #pragma unroll
                for (int i = 0; i < 16; i++)
                    tacc[i] = ffma2(s, w2[(ku + i) & 15], tacc[i]);
                // refill: slot (k&15) <- y[t0c+k+16]  (max idx 191 < 193)
                w2[ku] = yr[t0c + k + 16];
            }
        }

        float pe = 0.f, po = 0.f;
        #pragma unroll
        for (int i = 0; i < 16; i++) {
            float iv = invn[t0c + i];   // 0 kills t >= TOUT and padded region
            pe += fabsf(tacc[i].x) * iv;
            po += fabsf(tacc[i].y) * iv;
        }
        atomicAdd(&sacc[2 * lane],     pe);
        atomicAdd(&sacc[2 * lane + 1], po);
    }

    __syncthreads();
    if (tid < 64) atomicAdd(&g_acc[b * F_ + 64 * h + tid], sacc[tid]);

    // ---- last-CTA finish: apply per-filter factors + bias; reset state ----
    __threadfence();
    __syncthreads();
    if (tid == 0) {
        unsigned old = atomicAdd(&g_count, 1u);
        sflag = (old == NCTA2_ - 1) ? 1u : 0u;
    }
    __syncthreads();
    if (sflag) {
        float* wf_s = sm2;   // reuse smem (yil region, done)
        if (tid < F_) {
            int f = tid;
            float sc = 0.f, ss = 0.f;
            #pragma unroll 8
            for (int k = 0; k < K_; k++) { float v = conv_w[f * K_ + k]; sc += v * v; }
            #pragma unroll 8
            for (int c = 0; c < CIN_; c++) { float v = spat_w[f * CIN_ + c]; ss += v * v; }
            // scale = sqrt(CIN*K) = 64 exactly; fold 1/Tout for the mean
            wf_s[f] = weight[f] * 64.0f / (sqrtf(sc) * sqrtf(ss) * (float)TOUT_);
        }
        __syncthreads();
        if (tid < B_) {
            float s = 0.f;
            #pragma unroll 8
            for (int f = 0; f < F_; f++)
                s += bias[f] + wf_s[f] * __ldcg(&g_acc[tid * F_ + f]);
            out[tid] = s;
        }
        __syncthreads();
        for (int i = tid; i < B_ * F_; i += 256) g_acc[i] = 0.f;
        if (tid == 0) g_count = 0u;
    }
}

// ---------------------------------------------------------------------------
extern "C" void kernel_launch(void* const* d_in, const int* in_sizes, int n_in,
                              void* d_out, int out_size) {
    const float* x      = (const float*)d_in[0];  // [64,64,4096]
    const float* conv_w = (const float*)d_in[1];  // [128,64]
    const float* spat_w = (const float*)d_in[2];  // [128,64]
    const float* weight = (const float*)d_in[3];  // [128]
    const float* bias   = (const float*)d_in[4];  // [128]
    float* out = (float*)d_out;                   // [64]

    cudaFuncSetAttribute(k1_spatial,
                         cudaFuncAttributeMaxDynamicSharedMemorySize,
                         SM1_FLOATS * sizeof(float));
    cudaFuncSetAttribute(k2_temporal,
                         cudaFuncAttributeMaxDynamicSharedMemorySize,
                         SM2_FLOATS * sizeof(float));

    dim3 g1(NT1_, B_);
    k1_spatial<<<g1, 256, SM1_FLOATS * sizeof(float)>>>(x, spat_w);

    dim3 g2(NT2_, 2, B_);
    k2_temporal<<<g2, 256, SM2_FLOATS * sizeof(float)>>>(
        conv_w, spat_w, weight, bias, out);
}

// round 14
// speedup vs baseline: 1.5484x; 1.0107x over previous
#include <cuda_runtime.h>
#include <cuda_fp16.h>
#include <cstdint>

// Problem constants
#define B_    64
#define CIN_  64
#define T_    4096
#define F_    128
#define K_    64
#define TOUT_ 4033
#define NPAIR 64

// ---- K1 (spatial GEMM) ----
#define T1_   64
#define NT1_  64                  // 4096 / 64
#define WSS   132                 // weight row stride (floats): holds 128 f, mult of 4
#define XSS   68                  // x row stride (floats)
#define O1_W   0                  // ws 64*132 = 8448
#define O1_X   8448               // x  64*68  = 4352
#define SM1_FLOATS 12808          // 51232 B -> 3 CTAs/SM

// ---- K2 (temporal) ----
#define T2_   128
#define NT2_  32
#define NCTA2_ (NT2_ * 2 * B_)    // 4096
#define YIL2S 193                 // y tile row stride (float2)
#define CW2S  65                  // cw row stride (float2)
#define O2_Y    0                 // 32*193 f2 = 12352 floats
#define O2_CW   12352             // 32*65 f2 = 4160 floats
#define O2_SSQ  16512             // 192 (+pad)
#define O2_INV  16712             // 128
#define O2_SACC 16840             // 64
#define SM2_FLOATS 16912          // 67648 B -> 3 CTAs/SM

__device__ __align__(16) __half2 g_yh[(size_t)B_ * NPAIR * T_];  // [b][pair][t]
__device__ float    g_ssq[B_ * T_];
__device__ float    g_acc[B_ * F_];      // zero-init; reset by last CTA
__device__ unsigned g_count;             // zero-init; reset by last CTA

// ---------------------------------------------------------------------------
// Packed f32x2 FMA (SASS FFMA2 — only reachable via PTX)
// ---------------------------------------------------------------------------
__device__ __forceinline__ float2 ffma2(float2 a, float2 b, float2 c) {
    union U { float2 f; unsigned long long u; };
    U ua{a}, ub{b}, uc{c}, ur;
    asm("fma.rn.f32x2 %0, %1, %2, %3;" : "=l"(ur.u) : "l"(ua.u), "l"(ub.u), "l"(uc.u));
    return ur.f;
}

// ---------------------------------------------------------------------------
// K1: spatial GEMM y[b][f][t] = sum_c w[f,c] x[b,c,t]  + ssq; y stored fp16
// grid (NT1_, B_), 256 threads. No OOB anywhere (64*64 = 4096 exact).
// ---------------------------------------------------------------------------
__global__ __launch_bounds__(256, 3)
void k1_spatial(const float* __restrict__ x,
                const float* __restrict__ spat_w) {
    extern __shared__ float sm[];
    float* ws  = sm + O1_W;       // [64 c][WSS] transposed spat weights (128 f)
    float* x_s = sm + O1_X;       // [64 c][XSS]

    const int tid  = threadIdx.x;
    const int b    = blockIdx.y;
    const int t0g  = blockIdx.x * T1_;
    const int warp = tid >> 5;
    const int lane = tid & 31;

    const int wf4  = warp & 3;           // filter group (16 filters)
    const int wt   = warp >> 2;          // t half (32 t)
    const int tt   = lane & 7;
    const int fr   = lane >> 3;
    const int fthl = 16 * wf4 + 4 * fr;  // first filter within 64-group (even)
    const int tq0  = 32 * wt + 4 * tt;   // local t quad

    // ---- stage transposed weights: ws[c*WSS + f] = spat_w[f*64 + c] ----
    #pragma unroll
    for (int r = 0; r < 32; r++) {
        int idx = r * 256 + tid;         // 0..8191, coalesced read
        int f = idx >> 6, c = idx & 63;
        ws[c * WSS + f] = spat_w[idx];
    }
    // ---- stage x tile: 64 c x 64 t (1024 float4, 4 per thread) ----
    #pragma unroll
    for (int r = 0; r < 4; r++) {
        int q = r * 256 + tid;           // 0..1023
        int c = q >> 4, t4 = (q & 15) * 4;
        *(float4*)(x_s + c * XSS + t4) =
            *(const float4*)(x + (size_t)(b * CIN_ + c) * T_ + t0g + t4);
    }
    __syncthreads();

    if (tid < T1_) {
        float s = 0.f;
        #pragma unroll 8
        for (int c = 0; c < CIN_; c++) {
            float v = x_s[c * XSS + tid];
            s += v * v;
        }
        g_ssq[b * T_ + t0g + tid] = s;
    }

    float2 acc[2][4][2];
    #pragma unroll
    for (int g = 0; g < 2; g++)
        #pragma unroll
        for (int fi = 0; fi < 4; fi++)
            #pragma unroll
            for (int j = 0; j < 2; j++) acc[g][fi][j] = make_float2(0.f, 0.f);

    // software-pipelined c-loop: operands for c prefetched at c-1
    float4 xq = *(const float4*)(x_s + tq0);
    float4 wA = *(const float4*)(ws + fthl);
    float4 wB = *(const float4*)(ws + 64 + fthl);

    #pragma unroll 4
    for (int c = 0; c < CIN_; c++) {
        float4 xc = xq, wa = wA, wb = wB;
        if (c + 1 < CIN_) {
            xq = *(const float4*)(x_s + (c + 1) * XSS + tq0);
            wA = *(const float4*)(ws + (c + 1) * WSS + fthl);
            wB = *(const float4*)(ws + (c + 1) * WSS + 64 + fthl);
        }
        float2 xp0 = make_float2(xc.x, xc.y);
        float2 xp1 = make_float2(xc.z, xc.w);
        {
            float2 s0 = make_float2(wa.x, wa.x);
            float2 s1 = make_float2(wa.y, wa.y);
            float2 s2 = make_float2(wa.z, wa.z);
            float2 s3 = make_float2(wa.w, wa.w);
            acc[0][0][0] = ffma2(s0, xp0, acc[0][0][0]);
            acc[0][0][1] = ffma2(s0, xp1, acc[0][0][1]);
            acc[0][1][0] = ffma2(s1, xp0, acc[0][1][0]);
            acc[0][1][1] = ffma2(s1, xp1, acc[0][1][1]);
            acc[0][2][0] = ffma2(s2, xp0, acc[0][2][0]);
            acc[0][2][1] = ffma2(s2, xp1, acc[0][2][1]);
            acc[0][3][0] = ffma2(s3, xp0, acc[0][3][0]);
            acc[0][3][1] = ffma2(s3, xp1, acc[0][3][1]);
        }
        {
            float2 s0 = make_float2(wb.x, wb.x);
            float2 s1 = make_float2(wb.y, wb.y);
            float2 s2 = make_float2(wb.z, wb.z);
            float2 s3 = make_float2(wb.w, wb.w);
            acc[1][0][0] = ffma2(s0, xp0, acc[1][0][0]);
            acc[1][0][1] = ffma2(s0, xp1, acc[1][0][1]);
            acc[1][1][0] = ffma2(s1, xp0, acc[1][1][0]);
            acc[1][1][1] = ffma2(s1, xp1, acc[1][1][1]);
            acc[1][2][0] = ffma2(s2, xp0, acc[1][2][0]);
            acc[1][2][1] = ffma2(s2, xp1, acc[1][2][1]);
            acc[1][3][0] = ffma2(s3, xp0, acc[1][3][0]);
            acc[1][3][1] = ffma2(s3, xp1, acc[1][3][1]);
        }
    }

    // write filter-interleaved fp16 y: g_yh[b][P][t] = half2(y_{2P}[t], y_{2P+1}[t])
    {
        const size_t ybase = (size_t)b * NPAIR * T_;
        #pragma unroll
        for (int g = 0; g < 2; g++) {
            const int P0 = 32 * g + (fthl >> 1);
            #pragma unroll
            for (int pi = 0; pi < 2; pi++) {
                float2 e0 = acc[g][2 * pi][0], o0 = acc[g][2 * pi + 1][0];
                float2 e1 = acc[g][2 * pi][1], o1 = acc[g][2 * pi + 1][1];
                __half2 hv[4];
                hv[0] = __floats2half2_rn(e0.x, o0.x);   // t+0
                hv[1] = __floats2half2_rn(e0.y, o0.y);   // t+1
                hv[2] = __floats2half2_rn(e1.x, o1.x);   // t+2
                hv[3] = __floats2half2_rn(e1.y, o1.y);   // t+3
                *(float4*)(g_yh + ybase + (size_t)(P0 + pi) * T_ + t0g + tq0) =
                    *(float4*)hv;
            }
        }
    }
}

// ---------------------------------------------------------------------------
// K2: temporal conv + |.|*invn reduction; last CTA finishes.
// grid (NT2_, 2, B_), 256 threads.
// ---------------------------------------------------------------------------
__global__ __launch_bounds__(256, 3)
void k2_temporal(const float* __restrict__ conv_w,
                 const float* __restrict__ spat_w,
                 const float* __restrict__ weight,
                 const float* __restrict__ bias,
                 float* __restrict__ out) {
    extern __shared__ float sm2[];
    float2* yil2 = (float2*)(sm2 + O2_Y);    // [32 pairs][YIL2S]
    float2* cw2  = (float2*)(sm2 + O2_CW);   // [32 pairs][CW2S]
    float*  ssqs = sm2 + O2_SSQ;             // [192]
    float*  invn = sm2 + O2_INV;             // [128]
    float*  sacc = sm2 + O2_SACC;            // [64]
    __shared__ unsigned sflag;

    const int tid  = threadIdx.x;
    const int tile = blockIdx.x;
    const int h    = blockIdx.y;             // filter half (64 filters)
    const int b    = blockIdx.z;
    const int t0g  = tile * T2_;
    const int warp = tid >> 5;
    const int lane = tid & 31;
    const int t0c  = 16 * warp;

    if (tid < 64) sacc[tid] = 0.f;

    // ---- stage interleaved conv weights from raw conv_w (coalesced LDG) ----
    #pragma unroll
    for (int r = 0; r < 16; r++) {
        int idx = r * 256 + tid;             // 0..4095
        int fl = idx >> 6, k = idx & 63;
        float v = conv_w[(64 * h + fl) * K_ + k];
        ((float*)cw2)[(fl >> 1) * (2 * CW2S) + 2 * k + (fl & 1)] = v;
    }
    // ---- stage ssq (guarded) ----
    if (tid < 192) {
        int tg = t0g + tid;
        ssqs[tid] = (tg < T_) ? g_ssq[b * T_ + tg] : 0.f;
    }
    // ---- stage y tile (fp16 -> fp32 smem, warp-strided, guarded) ----
    {
        const __half2* ysrc = g_yh + (size_t)(b * NPAIR + 32 * h) * T_ + t0g;
        #pragma unroll
        for (int p = warp; p < 32; p += 8) {
            const __half2* yp = ysrc + (size_t)p * T_;
            #pragma unroll
            for (int t = lane; t < 192; t += 32)
                yil2[p * YIL2S + t] = (t0g + t < T_)
                    ? __half22float2(yp[t]) : make_float2(0.f, 0.f);
        }
    }
    __syncthreads();

    if (tid < T2_) {
        float s = 0.f;
        #pragma unroll 8
        for (int k = 0; k < K_; k++) s += ssqs[tid + k];
        invn[tid] = ((t0g + tid) < TOUT_ && s > 0.f) ? rsqrtf(s) : 0.f;
    }
    __syncthreads();

    // ---- temporal conv: lane = pair, warp -> 16 t, modular 16-slot window ----
    {
        const float2* yr  = yil2 + lane * YIL2S;
        const float2* cwr = cw2 + lane * CW2S;

        float2 tacc[16];
        #pragma unroll
        for (int i = 0; i < 16; i++) tacc[i] = make_float2(0.f, 0.f);

        float2 w2[16];
        #pragma unroll
        for (int i = 0; i < 16; i++) w2[i] = yr[t0c + i];

        float2 s = cwr[0];                   // cw prefetch (1 k ahead)
        for (int ko = 0; ko < 4; ko++) {
            #pragma unroll
            for (int ku = 0; ku < 16; ku++) {
                const int k = 16 * ko + ku;
                float2 scur = s;
                s = cwr[k + 1];              // k=63 reads pad slot 64 (never used)
                #pragma unroll
                for (int i = 0; i < 16; i++)
                    tacc[i] = ffma2(scur, w2[(ku + i) & 15], tacc[i]);
                // refill: slot (k&15) <- y[t0c+k+16]  (max idx 191 < 193)
                w2[ku] = yr[t0c + k + 16];
            }
        }

        float pe = 0.f, po = 0.f;
        #pragma unroll
        for (int i = 0; i < 16; i++) {
            float iv = invn[t0c + i];   // 0 kills t >= TOUT and padded region
            pe += fabsf(tacc[i].x) * iv;
            po += fabsf(tacc[i].y) * iv;
        }
        atomicAdd(&sacc[2 * lane],     pe);
        atomicAdd(&sacc[2 * lane + 1], po);
    }

    __syncthreads();
    if (tid < 64) atomicAdd(&g_acc[b * F_ + 64 * h + tid], sacc[tid]);

    // ---- last-CTA finish: apply per-filter factors + bias; reset state ----
    __threadfence();
    __syncthreads();
    if (tid == 0) {
        unsigned old = atomicAdd(&g_count, 1u);
        sflag = (old == NCTA2_ - 1) ? 1u : 0u;
    }
    __syncthreads();
    if (sflag) {
        float* wf_s = sm2;   // reuse smem (yil region, done)
        if (tid < F_) {
            int f = tid;
            float sc = 0.f, ss = 0.f;
            #pragma unroll 8
            for (int k = 0; k < K_; k++) { float v = conv_w[f * K_ + k]; sc += v * v; }
            #pragma unroll 8
            for (int c = 0; c < CIN_; c++) { float v = spat_w[f * CIN_ + c]; ss += v * v; }
            // scale = sqrt(CIN*K) = 64 exactly; fold 1/Tout for the mean
            wf_s[f] = weight[f] * 64.0f / (sqrtf(sc) * sqrtf(ss) * (float)TOUT_);
        }
        __syncthreads();
        if (tid < B_) {
            float s = 0.f;
            #pragma unroll 8
            for (int f = 0; f < F_; f++)
                s += bias[f] + wf_s[f] * __ldcg(&g_acc[tid * F_ + f]);
            out[tid] = s;
        }
        __syncthreads();
        for (int i = tid; i < B_ * F_; i += 256) g_acc[i] = 0.f;
        if (tid == 0) g_count = 0u;
    }
}

// ---------------------------------------------------------------------------
extern "C" void kernel_launch(void* const* d_in, const int* in_sizes, int n_in,
                              void* d_out, int out_size) {
    const float* x      = (const float*)d_in[0];  // [64,64,4096]
    const float* conv_w = (const float*)d_in[1];  // [128,64]
    const float* spat_w = (const float*)d_in[2];  // [128,64]
    const float* weight = (const float*)d_in[3];  // [128]
    const float* bias   = (const float*)d_in[4];  // [128]
    float* out = (float*)d_out;                   // [64]

    cudaFuncSetAttribute(k1_spatial,
                         cudaFuncAttributeMaxDynamicSharedMemorySize,
                         SM1_FLOATS * sizeof(float));
    cudaFuncSetAttribute(k2_temporal,
                         cudaFuncAttributeMaxDynamicSharedMemorySize,
                         SM2_FLOATS * sizeof(float));

    dim3 g1(NT1_, B_);
    k1_spatial<<<g1, 256, SM1_FLOATS * sizeof(float)>>>(x, spat_w);

    dim3 g2(NT2_, 2, B_);
    k2_temporal<<<g2, 256, SM2_FLOATS * sizeof(float)>>>(
        conv_w, spat_w, weight, bias, out);
}

// round 15
// speedup vs baseline: 2.0297x; 1.3109x over previous
#include <cuda_runtime.h>
#include <cuda_fp16.h>
#include <cstdint>

// Problem constants
#define B_    64
#define CIN_  64
#define T_    4096
#define F_    128
#define K_    64
#define TOUT_ 4033
#define NPAIR 64

// ---- K1 (HMMA spatial GEMM) ----
#define T1_   128
#define NT1_  32                  // 4096 / 128
#define XFS   132                 // x_s fp32 row stride (floats)
#define HS    72                  // fp16 tile row stride (halves); 144B, 16B-aligned
#define S1_XF 0                   // x_s fp32: 64*132*4 = 33792 B
#define S1_W  33792               // Ws fp16: 128*72*2 = 18432 B
#define S1_X  52224               // Xs fp16: 128*72*2 = 18432 B
#define S1_BYTES 70656

// ---- K2 (temporal) ----
#define T2_   128
#define NT2_  32
#define NCTA2_ (NT2_ * 2 * B_)    // 4096
#define YIL2S 193                 // y tile row stride (float2)
#define CW2S  65                  // cw row stride (float2)
#define O2_Y    0                 // 32*193 f2 = 12352 floats
#define O2_CW   12352             // 32*65 f2 = 4160 floats
#define O2_SSQ  16512             // 192 (+pad)
#define O2_INV  16712             // 128
#define O2_SACC 16840             // 64
#define SM2_FLOATS 16912          // 67648 B -> 3 CTAs/SM

__device__ __align__(16) __half2 g_yh[(size_t)B_ * NPAIR * T_];  // [b][pair][t]
__device__ float    g_ssq[B_ * T_];
__device__ float    g_acc[B_ * F_];      // zero-init; reset by last CTA
__device__ unsigned g_count;             // zero-init; reset by last CTA

// ---------------------------------------------------------------------------
// Packed f32x2 FMA (SASS FFMA2 — only reachable via PTX)
// ---------------------------------------------------------------------------
__device__ __forceinline__ float2 ffma2(float2 a, float2 b, float2 c) {
    union U { float2 f; unsigned long long u; };
    U ua{a}, ub{b}, uc{c}, ur;
    asm("fma.rn.f32x2 %0, %1, %2, %3;" : "=l"(ur.u) : "l"(ua.u), "l"(ub.u), "l"(uc.u));
    return ur.f;
}

__device__ __forceinline__ uint32_t smem_u32(const void* p) {
    uint32_t a;
    asm("{ .reg .u64 t; cvta.to.shared.u64 t, %1; cvt.u32.u64 %0, t; }"
        : "=r"(a) : "l"(p));
    return a;
}

// ---------------------------------------------------------------------------
// K1: spatial GEMM on HMMA (mma.sync m16n8k16 f16 -> f32 acc) + exact ssq.
// grid (NT1_, B_), 256 threads. No OOB (32*128 = 4096 exact).
// ---------------------------------------------------------------------------
__global__ __launch_bounds__(256, 2)
void k1_spatial(const float* __restrict__ x,
                const float* __restrict__ spat_w) {
    extern __shared__ char smem[];
    float*   x_s = (float*)(smem + S1_XF);     // [64 c][XFS]
    __half2* ws2 = (__half2*)(smem + S1_W);    // [128 f][HS/2 half2]
    __half2* xs2 = (__half2*)(smem + S1_X);    // [128 t][HS/2 half2]
    const uint32_t wsb = smem_u32(smem + S1_W);
    const uint32_t xsb = smem_u32(smem + S1_X);

    const int tid  = threadIdx.x;
    const int b    = blockIdx.y;
    const int t0g  = blockIdx.x * T1_;
    const int warp = tid >> 5;
    const int lane = tid & 31;

    // ---- stage x fp32 tile [64c][128t] (coalesced float4) ----
    #pragma unroll
    for (int r = 0; r < 8; r++) {
        int q = r * 256 + tid;           // 0..2047
        int c = q >> 5, t4 = (q & 31) * 4;
        *(float4*)(x_s + c * XFS + t4) =
            *(const float4*)(x + (size_t)(b * CIN_ + c) * T_ + t0g + t4);
    }
    // ---- stage W fp16: ws[f][c] (coalesced float2 -> half2) ----
    #pragma unroll
    for (int r = 0; r < 16; r++) {
        int idx = r * 256 + tid;         // 0..4095
        int f = idx >> 5, cp = idx & 31; // c pair
        float2 v = ((const float2*)spat_w)[idx];
        ws2[f * (HS / 2) + cp] = __floats2half2_rn(v.x, v.y);
    }
    __syncthreads();

    // ---- exact fp32 ssq ----
    if (tid < T1_) {
        float s = 0.f;
        #pragma unroll 8
        for (int c = 0; c < CIN_; c++) {
            float v = x_s[c * XFS + tid];
            s += v * v;
        }
        g_ssq[b * T_ + t0g + tid] = s;
    }
    // ---- transpose x -> Xs fp16 [t][c] (column LDS, conflict-free) ----
    {
        int t = tid & 127, ch = tid >> 7; // c halves: 0 or 1
        int c0 = 32 * ch;
        #pragma unroll
        for (int j = 0; j < 16; j++) {
            float v0 = x_s[(c0 + 2 * j)     * XFS + t];
            float v1 = x_s[(c0 + 2 * j + 1) * XFS + t];
            xs2[t * (HS / 2) + c0 / 2 + j] = __floats2half2_rn(v0, v1);
        }
    }
    __syncthreads();

    // ---- HMMA: warp owns 16 filters x 128 t ----
    const int m0 = 16 * warp;
    float d[16][4];
    #pragma unroll
    for (int nt = 0; nt < 16; nt++)
        #pragma unroll
        for (int i = 0; i < 4; i++) d[nt][i] = 0.f;

    // per-lane ldmatrix address components (halves)
    const int a_off = (m0 + (lane & 15)) * HS + (lane >> 4) * 8;
    const int b_off = (8 * (lane >> 4) + (lane & 7)) * HS + 8 * ((lane >> 3) & 1);

    #pragma unroll
    for (int ks = 0; ks < 4; ks++) {
        uint32_t a0, a1, a2, a3;
        {
            uint32_t addr = wsb + 2 * (a_off + 16 * ks);
            asm volatile("ldmatrix.sync.aligned.m8n8.x4.shared.b16 {%0,%1,%2,%3}, [%4];"
                : "=r"(a0), "=r"(a1), "=r"(a2), "=r"(a3) : "r"(addr));
        }
        #pragma unroll
        for (int j = 0; j < 8; j++) {     // n-tile pairs (nt = 2j, 2j+1)
            uint32_t b0, b1, b2, b3;
            uint32_t addr = xsb + 2 * (b_off + (16 * j) * HS + 16 * ks);
            asm volatile("ldmatrix.sync.aligned.m8n8.x4.shared.b16 {%0,%1,%2,%3}, [%4];"
                : "=r"(b0), "=r"(b1), "=r"(b2), "=r"(b3) : "r"(addr));
            asm volatile(
                "mma.sync.aligned.m16n8k16.row.col.f32.f16.f16.f32 "
                "{%0,%1,%2,%3}, {%4,%5,%6,%7}, {%8,%9}, {%0,%1,%2,%3};"
                : "+f"(d[2*j][0]), "+f"(d[2*j][1]), "+f"(d[2*j][2]), "+f"(d[2*j][3])
                : "r"(a0), "r"(a1), "r"(a2), "r"(a3), "r"(b0), "r"(b1));
            asm volatile(
                "mma.sync.aligned.m16n8k16.row.col.f32.f16.f16.f32 "
                "{%0,%1,%2,%3}, {%4,%5,%6,%7}, {%8,%9}, {%0,%1,%2,%3};"
                : "+f"(d[2*j+1][0]), "+f"(d[2*j+1][1]), "+f"(d[2*j+1][2]), "+f"(d[2*j+1][3])
                : "r"(a0), "r"(a1), "r"(a2), "r"(a3), "r"(b2), "r"(b3));
        }
    }

    // ---- epilogue: pair even/odd filters via shfl, write half2 y ----
    {
        const int gid  = lane >> 2;      // 0..7  (row within m-tile)
        const int tid4 = lane & 3;       // col pair
        const bool wr  = (gid & 1) == 0; // even-gid lanes store
        const size_t ybase = (size_t)b * NPAIR * T_;
        const int Plo = 8 * warp + (gid >> 1);        // pair for rows gid,gid+1
        #pragma unroll
        for (int nt = 0; nt < 16; nt++) {
            float p0 = __shfl_xor_sync(0xffffffffu, d[nt][0], 4);
            float p1 = __shfl_xor_sync(0xffffffffu, d[nt][1], 4);
            float p2 = __shfl_xor_sync(0xffffffffu, d[nt][2], 4);
            float p3 = __shfl_xor_sync(0xffffffffu, d[nt][3], 4);
            if (wr) {
                int t = t0g + 8 * nt + 2 * tid4;
                __half2 h0 = __floats2half2_rn(d[nt][0], p0);  // t
                __half2 h1 = __floats2half2_rn(d[nt][1], p1);  // t+1
                __half2 h2 = __floats2half2_rn(d[nt][2], p2);  // rows +8, t
                __half2 h3 = __floats2half2_rn(d[nt][3], p3);  // rows +8, t+1
                float2 lo, hi;
                memcpy(&lo, &h0, 4); memcpy((char*)&lo + 4, &h1, 4);
                memcpy(&hi, &h2, 4); memcpy((char*)&hi + 4, &h3, 4);
                *(float2*)(g_yh + ybase + (size_t)Plo * T_ + t)       = lo;
                *(float2*)(g_yh + ybase + (size_t)(Plo + 4) * T_ + t) = hi;
            }
        }
    }
}

// ---------------------------------------------------------------------------
// K2: temporal conv + |.|*invn reduction; last CTA finishes. (R14, unchanged)
// grid (NT2_, 2, B_), 256 threads.
// ---------------------------------------------------------------------------
__global__ __launch_bounds__(256, 3)
void k2_temporal(const float* __restrict__ conv_w,
                 const float* __restrict__ spat_w,
                 const float* __restrict__ weight,
                 const float* __restrict__ bias,
                 float* __restrict__ out) {
    extern __shared__ float sm2[];
    float2* yil2 = (float2*)(sm2 + O2_Y);    // [32 pairs][YIL2S]
    float2* cw2  = (float2*)(sm2 + O2_CW);   // [32 pairs][CW2S]
    float*  ssqs = sm2 + O2_SSQ;             // [192]
    float*  invn = sm2 + O2_INV;             // [128]
    float*  sacc = sm2 + O2_SACC;            // [64]
    __shared__ unsigned sflag;

    const int tid  = threadIdx.x;
    const int tile = blockIdx.x;
    const int h    = blockIdx.y;             // filter half (64 filters)
    const int b    = blockIdx.z;
    const int t0g  = tile * T2_;
    const int warp = tid >> 5;
    const int lane = tid & 31;
    const int t0c  = 16 * warp;

    if (tid < 64) sacc[tid] = 0.f;

    // ---- stage interleaved conv weights from raw conv_w (coalesced LDG) ----
    #pragma unroll
    for (int r = 0; r < 16; r++) {
        int idx = r * 256 + tid;             // 0..4095
        int fl = idx >> 6, k = idx & 63;
        float v = conv_w[(64 * h + fl) * K_ + k];
        ((float*)cw2)[(fl >> 1) * (2 * CW2S) + 2 * k + (fl & 1)] = v;
    }
    // ---- stage ssq (guarded) ----
    if (tid < 192) {
        int tg = t0g + tid;
        ssqs[tid] = (tg < T_) ? g_ssq[b * T_ + tg] : 0.f;
    }
    // ---- stage y tile (fp16 -> fp32 smem, warp-strided, guarded) ----
    {
        const __half2* ysrc = g_yh + (size_t)(b * NPAIR + 32 * h) * T_ + t0g;
        #pragma unroll
        for (int p = warp; p < 32; p += 8) {
            const __half2* yp = ysrc + (size_t)p * T_;
            #pragma unroll
            for (int t = lane; t < 192; t += 32)
                yil2[p * YIL2S + t] = (t0g + t < T_)
                    ? __half22float2(yp[t]) : make_float2(0.f, 0.f);
        }
    }
    __syncthreads();

    if (tid < T2_) {
        float s = 0.f;
        #pragma unroll 8
        for (int k = 0; k < K_; k++) s += ssqs[tid + k];
        invn[tid] = ((t0g + tid) < TOUT_ && s > 0.f) ? rsqrtf(s) : 0.f;
    }
    __syncthreads();

    // ---- temporal conv: lane = pair, warp -> 16 t, modular 16-slot window ----
    {
        const float2* yr  = yil2 + lane * YIL2S;
        const float2* cwr = cw2 + lane * CW2S;

        float2 tacc[16];
        #pragma unroll
        for (int i = 0; i < 16; i++) tacc[i] = make_float2(0.f, 0.f);

        float2 w2[16];
        #pragma unroll
        for (int i = 0; i < 16; i++) w2[i] = yr[t0c + i];

        float2 s = cwr[0];                   // cw prefetch (1 k ahead)
        for (int ko = 0; ko < 4; ko++) {
            #pragma unroll
            for (int ku = 0; ku < 16; ku++) {
                const int k = 16 * ko + ku;
                float2 scur = s;
                s = cwr[k + 1];              // k=63 reads pad slot 64 (never used)
                #pragma unroll
                for (int i = 0; i < 16; i++)
                    tacc[i] = ffma2(scur, w2[(ku + i) & 15], tacc[i]);
                // refill: slot (k&15) <- y[t0c+k+16]  (max idx 191 < 193)
                w2[ku] = yr[t0c + k + 16];
            }
        }

        float pe = 0.f, po = 0.f;
        #pragma unroll
        for (int i = 0; i < 16; i++) {
            float iv = invn[t0c + i];   // 0 kills t >= TOUT and padded region
            pe += fabsf(tacc[i].x) * iv;
            po += fabsf(tacc[i].y) * iv;
        }
        atomicAdd(&sacc[2 * lane],     pe);
        atomicAdd(&sacc[2 * lane + 1], po);
    }

    __syncthreads();
    if (tid < 64) atomicAdd(&g_acc[b * F_ + 64 * h + tid], sacc[tid]);

    // ---- last-CTA finish: apply per-filter factors + bias; reset state ----
    __threadfence();
    __syncthreads();
    if (tid == 0) {
        unsigned old = atomicAdd(&g_count, 1u);
        sflag = (old == NCTA2_ - 1) ? 1u : 0u;
    }
    __syncthreads();
    if (sflag) {
        float* wf_s = sm2;   // reuse smem (yil region, done)
        if (tid < F_) {
            int f = tid;
            float sc = 0.f, ss = 0.f;
            #pragma unroll 8
            for (int k = 0; k < K_; k++) { float v = conv_w[f * K_ + k]; sc += v * v; }
            #pragma unroll 8
            for (int c = 0; c < CIN_; c++) { float v = spat_w[f * CIN_ + c]; ss += v * v; }
            // scale = sqrt(CIN*K) = 64 exactly; fold 1/Tout for the mean
            wf_s[f] = weight[f] * 64.0f / (sqrtf(sc) * sqrtf(ss) * (float)TOUT_);
        }
        __syncthreads();
        if (tid < B_) {
            float s = 0.f;
            #pragma unroll 8
            for (int f = 0; f < F_; f++)
                s += bias[f] + wf_s[f] * __ldcg(&g_acc[tid * F_ + f]);
            out[tid] = s;
        }
        __syncthreads();
        for (int i = tid; i < B_ * F_; i += 256) g_acc[i] = 0.f;
        if (tid == 0) g_count = 0u;
    }
}

// ---------------------------------------------------------------------------
extern "C" void kernel_launch(void* const* d_in, const int* in_sizes, int n_in,
                              void* d_out, int out_size) {
    const float* x      = (const float*)d_in[0];  // [64,64,4096]
    const float* conv_w = (const float*)d_in[1];  // [128,64]
    const float* spat_w = (const float*)d_in[2];  // [128,64]
    const float* weight = (const float*)d_in[3];  // [128]
    const float* bias   = (const float*)d_in[4];  // [128]
    float* out = (float*)d_out;                   // [64]

    cudaFuncSetAttribute(k1_spatial,
                         cudaFuncAttributeMaxDynamicSharedMemorySize, S1_BYTES);
    cudaFuncSetAttribute(k2_temporal,
                         cudaFuncAttributeMaxDynamicSharedMemorySize,
                         SM2_FLOATS * sizeof(float));

    dim3 g1(NT1_, B_);
    k1_spatial<<<g1, 256, S1_BYTES>>>(x, spat_w);

    dim3 g2(NT2_, 2, B_);
    k2_temporal<<<g2, 256, SM2_FLOATS * sizeof(float)>>>(
        conv_w, spat_w, weight, bias, out);
}